// round 16
// baseline (speedup 1.0000x reference)
#include <cuda_runtime.h>
#include <cuda_fp16.h>
#include <math.h>
#include <stdint.h>

#define TOK   8192
#define DIM   1024
#define NEXP  8
#define HID   4096
#define AROWS 9216   // TOK + 8 experts * up-to-127 alignment padding

// ------------------------- device scratch (no cudaMalloc) -------------------
__device__ int g_expert[TOK];
__device__ int g_counts[NEXP];
__device__ int g_offsets[NEXP];   // 128-aligned segment starts
__device__ int g_cursor[NEXP];
__device__ int g_tok[AROWS];      // permuted row -> token id
__device__ int g_pos[TOK];        // token id -> permuted row
// chunked fp16 operand layouts: [K/64 blocks][rows][64], smem SW-swizzle
// pre-applied within each 64-element row (16B group g stored at g ^ (row&7)).
__device__ __half g_xa [(size_t)(DIM / 64) * AROWS * 64];
__device__ __half g_ha [(size_t)(HID / 64) * AROWS * 64];
__device__ __half g_w1t[(size_t)NEXP * (DIM / 64) * HID * 64];  // [e][kb][n][64]
__device__ __half g_w2t[(size_t)NEXP * (HID / 64) * DIM * 64];  // [e][kb][n][64]

// ------------------------- helpers ------------------------------------------
__device__ __forceinline__ uint32_t smem_u32(const void* p) {
    uint32_t a;
    asm("{ .reg .u64 t; cvta.to.shared.u64 t, %1; cvt.u32.u64 %0, t; }" : "=r"(a) : "l"(p));
    return a;
}
#define LDSM4(r, addr)                                                          \
    asm volatile("ldmatrix.sync.aligned.m8n8.x4.shared.b16 {%0,%1,%2,%3}, [%4];" \
        : "=r"((r)[0]), "=r"((r)[1]), "=r"((r)[2]), "=r"((r)[3]) : "r"(addr))
#define MMA_F16(d, a, b)                                                        \
    asm volatile("mma.sync.aligned.m16n8k16.row.col.f32.f16.f16.f32 "           \
        "{%0,%1,%2,%3},{%4,%5,%6,%7},{%8,%9},{%0,%1,%2,%3};"                    \
        : "+f"((d)[0]), "+f"((d)[1]), "+f"((d)[2]), "+f"((d)[3])                 \
        : "r"((a)[0]), "r"((a)[1]), "r"((a)[2]), "r"((a)[3]),                    \
          "r"((b)[0]), "r"((b)[1]))
#define MBAR_INIT(mb, c)                                                        \
    asm volatile("mbarrier.init.shared.b64 [%0], %1;" :: "r"(mb), "r"(c) : "memory")
#define MBAR_EXPECT_TX(mb, bytes)                                               \
    asm volatile("mbarrier.arrive.expect_tx.shared.b64 _, [%0], %1;"            \
        :: "r"(mb), "r"(bytes) : "memory")
#define CP_BULK(dst, src, sz, mb)                                               \
    asm volatile("cp.async.bulk.shared::cta.global.mbarrier::complete_tx::bytes " \
        "[%0], [%1], %2, [%3];" :: "r"(dst), "l"(src), "r"(sz), "r"(mb) : "memory")
#define MBAR_WAIT(mb, ph)                                                       \
    asm volatile("{ .reg .pred P1; MW_%=: mbarrier.try_wait.parity.shared.b64 "  \
        "P1, [%0], %1; @P1 bra.uni MD_%=; bra.uni MW_%=; MD_%=: }"               \
        :: "r"(mb), "r"(ph) : "memory")

// swizzled byte offset of 16B chunk within a [rows]x64-fp16 tile (128B rows)
__device__ __forceinline__ uint32_t swz(uint32_t row, uint32_t chunk) {
    return row * 128u + (((chunk ^ row) & 7u) << 4);
}

// ------------------------- small kernels ------------------------------------
__global__ void k_init() {
    int i = threadIdx.x;
    if (i < NEXP) { g_counts[i] = 0; g_cursor[i] = 0; }
}

// router: one warp handles 8 tokens -> Wr is read once per 8 tokens (8x less
// L1 traffic than one-token-per-warp). acc[t][e] in registers, butterfly
// reduce, lanes 0..7 emit argmax for their token.
__global__ void k_router(const float* __restrict__ x,
                         const float* __restrict__ Wr,
                         const float* __restrict__ br) {
    int gw   = (blockIdx.x * blockDim.x + threadIdx.x) >> 5;
    int lane = threadIdx.x & 31;
    int t0   = gw * 8;
    if (t0 >= TOK) return;

    float acc[8][8];
#pragma unroll
    for (int t = 0; t < 8; t++)
#pragma unroll
        for (int e = 0; e < NEXP; e++) acc[t][e] = 0.f;

    for (int it = 0; it < DIM / 32; it++) {
        int d = it * 32 + lane;
        float4 w0 = *(const float4*)(Wr + (size_t)d * NEXP);
        float4 w1 = *(const float4*)(Wr + (size_t)d * NEXP + 4);
#pragma unroll
        for (int t = 0; t < 8; t++) {
            float xv = x[(size_t)(t0 + t) * DIM + d];
            acc[t][0] += xv * w0.x; acc[t][1] += xv * w0.y;
            acc[t][2] += xv * w0.z; acc[t][3] += xv * w0.w;
            acc[t][4] += xv * w1.x; acc[t][5] += xv * w1.y;
            acc[t][6] += xv * w1.z; acc[t][7] += xv * w1.w;
        }
    }
#pragma unroll
    for (int t = 0; t < 8; t++)
#pragma unroll
        for (int e = 0; e < NEXP; e++)
#pragma unroll
            for (int off = 16; off > 0; off >>= 1)
                acc[t][e] += __shfl_xor_sync(0xFFFFFFFFu, acc[t][e], off);

    if (lane < 8) {
        int t = lane;
        float best = acc[t][0] + br[0]; int bi = 0;
#pragma unroll
        for (int e = 1; e < NEXP; e++) {
            float v = acc[t][e] + br[e];
            if (v > best) { best = v; bi = e; }
        }
        g_expert[t0 + t] = bi;
        atomicAdd(&g_counts[bi], 1);
    }
}

__global__ void k_scan() {
    if (threadIdx.x == 0) {
        int s = 0;
        for (int e = 0; e < NEXP; e++) {
            g_offsets[e] = s;
            s += (g_counts[e] + 127) & ~127;    // 128-aligned segments
        }
    }
}

__global__ void k_scatter() {
    int t = blockIdx.x * blockDim.x + threadIdx.x;
    if (t >= TOK) return;
    int e = g_expert[t];
    int pos = g_offsets[e] + atomicAdd(&g_cursor[e], 1);
    g_tok[pos] = t;
    g_pos[t]   = pos;
}

// gather + convert x rows into chunked swizzled fp16 layout
__global__ void k_gather16(const float* __restrict__ x) {
    int t   = blockIdx.x;          // token id
    int pos = g_pos[t];
    int b   = threadIdx.x >> 3;    // k-block 0..15
    int c   = threadIdx.x & 7;     // dest 16B chunk position 0..7
    int cc  = c ^ (pos & 7);       // source chunk
    const float4* src = (const float4*)(x + (size_t)t * DIM + b * 64 + cc * 8);
    float4 v0 = src[0], v1 = src[1];
    __half2 h0 = __floats2half2_rn(v0.x, v0.y);
    __half2 h1 = __floats2half2_rn(v0.z, v0.w);
    __half2 h2 = __floats2half2_rn(v1.x, v1.y);
    __half2 h3 = __floats2half2_rn(v1.z, v1.w);
    uint4 o;
    o.x = *(uint32_t*)&h0; o.y = *(uint32_t*)&h1;
    o.z = *(uint32_t*)&h2; o.w = *(uint32_t*)&h3;
    *(uint4*)(g_xa + ((size_t)b * AROWS + pos) * 64 + c * 8) = o;
}

// weights: [e][R=k][C=n] fp32 -> chunked [e][R/64][C][64] fp16, swizzled
__global__ void k_tconv(const float* __restrict__ src,
                        __half* __restrict__ dst, int R, int C) {
    __shared__ float tile[64][33];
    const int e  = blockIdx.z;
    const int kb = blockIdx.y;         // k-block
    const int n0 = blockIdx.x * 32;
    const int KB = R / 64;
    const float* s = src + (size_t)e * R * C + (size_t)kb * 64 * C + n0;
    int tx = threadIdx.x & 31, ty = threadIdx.x >> 5;
#pragma unroll
    for (int i = 0; i < 8; i++)
        tile[ty * 8 + i][tx] = s[(size_t)(ty * 8 + i) * C + tx];
    __syncthreads();
    int c  = threadIdx.x & 7;          // dest chunk position
    int nn = threadIdx.x >> 3;         // 0..31
    int n  = n0 + nn;
    int cc = c ^ (n & 7);              // source chunk
    __half2 h0 = __floats2half2_rn(tile[cc * 8 + 0][nn], tile[cc * 8 + 1][nn]);
    __half2 h1 = __floats2half2_rn(tile[cc * 8 + 2][nn], tile[cc * 8 + 3][nn]);
    __half2 h2 = __floats2half2_rn(tile[cc * 8 + 4][nn], tile[cc * 8 + 5][nn]);
    __half2 h3 = __floats2half2_rn(tile[cc * 8 + 6][nn], tile[cc * 8 + 7][nn]);
    uint4 o;
    o.x = *(uint32_t*)&h0; o.y = *(uint32_t*)&h1;
    o.z = *(uint32_t*)&h2; o.w = *(uint32_t*)&h3;
    *(uint4*)(dst + (((size_t)e * KB + kb) * C + n) * 64 + c * 8) = o;
}

// ------------------------- fp16 HMMA grouped GEMM, bulk producer -------------
// D = A*B. 128x128 CTA tile, 4 warps (128 threads) of 64x64 warp tiles,
// BK=64, 3-stage pipeline (32KB/stage), 2 CTAs/SM.
// Iter c computes stage c%3 and (after the barrier) refills stage (c+2)%3.
template<int KB, int NTOT, bool WRITE_H, bool SCATTER_OUT>
__global__ __launch_bounds__(128, 2)
void k_mma(const __half* __restrict__ A, const __half* __restrict__ B,
           const float* __restrict__ bias, float* __restrict__ OutF,
           __half* __restrict__ Hout) {
    extern __shared__ char smem[];
    __shared__ uint64_t mbar[3];
    const int e   = blockIdx.z;
    const int cnt = g_counts[e];
    const int row0 = blockIdx.y * 128;
    if (row0 >= cnt) return;
    const int base = g_offsets[e];           // 128-aligned
    const int col0 = blockIdx.x * 128;

    const uint32_t sb = smem_u32(smem);
    const int tid  = threadIdx.x;
    const int lane = tid & 31, warp = tid >> 5;
    const int wm = warp & 1, wn = warp >> 1;        // 2 x 2 warp grid, 64x64 tiles

    if (tid == 0) {
#pragma unroll
        for (int s = 0; s < 3; s++) MBAR_INIT(smem_u32(&mbar[s]), 1);
    }
    __syncthreads();

    const __half* Abase = A + ((size_t)base + row0) * 64;
    const __half* Bbase = B + ((size_t)e * KB * NTOT + col0) * 64;
    auto issue = [&](int c) {
        const int s = c % 3;
        const uint32_t st = sb + (uint32_t)s * 32768u;
        const uint32_t mb = smem_u32(&mbar[s]);
        MBAR_EXPECT_TX(mb, 32768u);
        CP_BULK(st,          Abase + (size_t)c * AROWS * 64, 16384u, mb);
        CP_BULK(st + 16384u, Bbase + (size_t)c * NTOT * 64,  16384u, mb);
    };
    if (tid == 0) { issue(0); issue(1); }

    // ---- consumer (ldmatrix) mapping ----
    const uint32_t g  = (uint32_t)lane >> 3;
    const uint32_t lr = (uint32_t)lane & 7;
    const uint32_t rowA = (uint32_t)(wm * 64) + (g & 1) * 8 + lr;
    const uint32_t chA  = g >> 1;
    const uint32_t rowB = (uint32_t)(wn * 64) + (g >> 1) * 8 + lr;
    const uint32_t chB  = g & 1;

    float acc[4][8][4];
#pragma unroll
    for (int i = 0; i < 4; i++)
#pragma unroll
        for (int j = 0; j < 8; j++)
#pragma unroll
            for (int q = 0; q < 4; q++) acc[i][j][q] = 0.f;

    int st_s = 0, ph = 0;
    for (int c = 0; c < KB; c++) {
        MBAR_WAIT(smem_u32(&mbar[st_s]), (uint32_t)ph);

        const uint32_t stc = sb + (uint32_t)st_s * 32768u;
#pragma unroll
        for (int kk = 0; kk < 4; kk++) {
            uint32_t ah[4][4], bb[8][2];
#pragma unroll
            for (int i = 0; i < 4; i++)
                LDSM4(ah[i], stc + swz(rowA + i * 16, kk * 2 + chA));
#pragma unroll
            for (int p = 0; p < 4; p++) {
                uint32_t t4[4];
                LDSM4(t4, stc + 16384u + swz(rowB + p * 16, kk * 2 + chB));
                bb[p * 2][0] = t4[0]; bb[p * 2][1] = t4[1];
                bb[p * 2 + 1][0] = t4[2]; bb[p * 2 + 1][1] = t4[3];
            }
#pragma unroll
            for (int i = 0; i < 4; i++)
#pragma unroll
                for (int j = 0; j < 8; j++) MMA_F16(acc[i][j], ah[i], bb[j]);
        }

        __syncthreads();                       // all warps done with this stage
        if (tid == 0 && c + 2 < KB) issue(c + 2);
        if (++st_s == 3) { st_s = 0; ph ^= 1; }
    }

    // ---- epilogue ----
    const int qr = lane >> 2;
    const int qc = (lane & 3) * 2;
#pragma unroll
    for (int i = 0; i < 4; i++) {
#pragma unroll
        for (int h = 0; h < 2; h++) {
            const int grow = row0 + wm * 64 + i * 16 + qr + h * 8;
            if (grow >= cnt) continue;
#pragma unroll
            for (int j = 0; j < 8; j++) {
                const int col = col0 + wn * 64 + j * 8 + qc;
                float v0 = acc[i][j][h * 2 + 0] + bias[(size_t)e * NTOT + col];
                float v1 = acc[i][j][h * 2 + 1] + bias[(size_t)e * NTOT + col + 1];
                if (WRITE_H) {
                    v0 = 0.5f * v0 * (1.0f + erff(v0 * 0.70710678118654752f));
                    v1 = 0.5f * v1 * (1.0f + erff(v1 * 0.70710678118654752f));
                    size_t row = (size_t)(base + grow);
                    int hb = col >> 6;
                    int cc = (col >> 3) & 7;
                    size_t o = ((size_t)hb * AROWS + row) * 64 +
                               (((uint32_t)cc ^ (uint32_t)(row & 7)) << 3) + qc;
                    __half2 hv = __floats2half2_rn(v0, v1);
                    *(__half2*)(Hout + o) = hv;
                } else {
                    size_t orow = SCATTER_OUT ? (size_t)g_tok[base + grow]
                                              : (size_t)(base + grow);
                    *(float2*)(OutF + orow * NTOT + col) = make_float2(v0, v1);
                }
            }
        }
    }
}

// ------------------------- launch --------------------------------------------
extern "C" void kernel_launch(void* const* d_in, const int* in_sizes, int n_in,
                              void* d_out, int out_size) {
    const float* x  = (const float*)d_in[0];
    const float* Wr = (const float*)d_in[1];
    const float* br = (const float*)d_in[2];
    const float* W1 = (const float*)d_in[3];
    const float* b1 = (const float*)d_in[4];
    const float* W2 = (const float*)d_in[5];
    const float* b2 = (const float*)d_in[6];
    float* out = (float*)d_out;

    __half *xa, *ha, *w1t, *w2t;
    cudaGetSymbolAddress((void**)&xa,  g_xa);
    cudaGetSymbolAddress((void**)&ha,  g_ha);
    cudaGetSymbolAddress((void**)&w1t, g_w1t);
    cudaGetSymbolAddress((void**)&w2t, g_w2t);

    // lazily-created side stream + fork/join events (host objects only; no
    // device memory). The captured WORK is identical on every call.
    static cudaStream_t s2 = nullptr;
    static cudaEvent_t ev0 = nullptr, ev1 = nullptr, ev2 = nullptr;
    if (!s2) {
        cudaStreamCreateWithFlags(&s2, cudaStreamNonBlocking);
        cudaEventCreateWithFlags(&ev0, cudaEventDisableTiming);
        cudaEventCreateWithFlags(&ev1, cudaEventDisableTiming);
        cudaEventCreateWithFlags(&ev2, cudaEventDisableTiming);
    }

    const int SMEM_DYN = 3 * 32768;   // 96KB
    cudaFuncSetAttribute((const void*)k_mma<DIM / 64, HID, true,  false>,
                         cudaFuncAttributeMaxDynamicSharedMemorySize, SMEM_DYN);
    cudaFuncSetAttribute((const void*)k_mma<HID / 64, DIM, false, true>,
                         cudaFuncAttributeMaxDynamicSharedMemorySize, SMEM_DYN);

    // fork: weight-conversion stream (independent of the router chain)
    cudaEventRecord(ev0, 0);
    cudaStreamWaitEvent(s2, ev0, 0);
    k_tconv<<<dim3(HID / 32, DIM / 64, NEXP), 256, 0, s2>>>(W1, w1t, DIM, HID);
    cudaEventRecord(ev1, s2);
    k_tconv<<<dim3(DIM / 32, HID / 64, NEXP), 256, 0, s2>>>(W2, w2t, HID, DIM);
    cudaEventRecord(ev2, s2);

    // main chain: router -> permutation -> gather
    k_init<<<1, 32>>>();
    k_router<<<TOK / 64, 256>>>(x, Wr, br);    // 8 warps/block, 8 tokens/warp
    k_scan<<<1, 32>>>();
    k_scatter<<<TOK / 256, 256>>>();
    k_gather16<<<TOK, 128>>>(x);

    // GEMM1 needs w1t; GEMM2 needs w2t (tconv2 overlaps GEMM1)
    cudaStreamWaitEvent(0, ev1, 0);
    k_mma<DIM / 64, HID, true,  false>
        <<<dim3(HID / 128, TOK / 128, NEXP), 128, SMEM_DYN>>>(xa, w1t, b1, nullptr, ha);
    cudaStreamWaitEvent(0, ev2, 0);
    k_mma<HID / 64, DIM, false, true>
        <<<dim3(DIM / 128, TOK / 128, NEXP), 128, SMEM_DYN>>>(ha, w2t, b2, out, nullptr);
}

// round 17
// speedup vs baseline: 1.0065x; 1.0065x over previous
#include <cuda_runtime.h>
#include <cuda_fp16.h>
#include <math.h>
#include <stdint.h>

#define TOK   8192
#define DIM   1024
#define NEXP  8
#define HID   4096
#define AROWS 9216   // TOK + 8 experts * up-to-127 alignment padding

// ------------------------- device scratch (no cudaMalloc) -------------------
__device__ int g_expert[TOK];
__device__ int g_counts[NEXP];
__device__ int g_offsets[NEXP];   // 128-aligned segment starts
__device__ int g_cursor[NEXP];
__device__ int g_tok[AROWS];      // permuted row -> token id
__device__ int g_pos[TOK];        // token id -> permuted row
// chunked fp16 operand layouts: [K/64 blocks][rows][64], smem SW-swizzle
// pre-applied within each 64-element row (16B group g stored at g ^ (row&7)).
__device__ __half g_xa [(size_t)(DIM / 64) * AROWS * 64];
__device__ __half g_ha [(size_t)(HID / 64) * AROWS * 64];
__device__ __half g_w1t[(size_t)NEXP * (DIM / 64) * HID * 64];  // [e][kb][n][64]
__device__ __half g_w2t[(size_t)NEXP * (HID / 64) * DIM * 64];  // [e][kb][n][64]

// ------------------------- helpers ------------------------------------------
__device__ __forceinline__ uint32_t smem_u32(const void* p) {
    uint32_t a;
    asm("{ .reg .u64 t; cvta.to.shared.u64 t, %1; cvt.u32.u64 %0, t; }" : "=r"(a) : "l"(p));
    return a;
}
#define LDSM4(r, addr)                                                          \
    asm volatile("ldmatrix.sync.aligned.m8n8.x4.shared.b16 {%0,%1,%2,%3}, [%4];" \
        : "=r"((r)[0]), "=r"((r)[1]), "=r"((r)[2]), "=r"((r)[3]) : "r"(addr))
#define MMA_F16(d, a, b)                                                        \
    asm volatile("mma.sync.aligned.m16n8k16.row.col.f32.f16.f16.f32 "           \
        "{%0,%1,%2,%3},{%4,%5,%6,%7},{%8,%9},{%0,%1,%2,%3};"                    \
        : "+f"((d)[0]), "+f"((d)[1]), "+f"((d)[2]), "+f"((d)[3])                 \
        : "r"((a)[0]), "r"((a)[1]), "r"((a)[2]), "r"((a)[3]),                    \
          "r"((b)[0]), "r"((b)[1]))
#define MBAR_INIT(mb, c)                                                        \
    asm volatile("mbarrier.init.shared.b64 [%0], %1;" :: "r"(mb), "r"(c) : "memory")
#define MBAR_EXPECT_TX(mb, bytes)                                               \
    asm volatile("mbarrier.arrive.expect_tx.shared.b64 _, [%0], %1;"            \
        :: "r"(mb), "r"(bytes) : "memory")
#define CP_BULK(dst, src, sz, mb)                                               \
    asm volatile("cp.async.bulk.shared::cta.global.mbarrier::complete_tx::bytes " \
        "[%0], [%1], %2, [%3];" :: "r"(dst), "l"(src), "r"(sz), "r"(mb) : "memory")
#define MBAR_WAIT(mb, ph)                                                       \
    asm volatile("{ .reg .pred P1; MW_%=: mbarrier.try_wait.parity.shared.b64 "  \
        "P1, [%0], %1; @P1 bra.uni MD_%=; bra.uni MW_%=; MD_%=: }"               \
        :: "r"(mb), "r"(ph) : "memory")

// swizzled byte offset of 16B chunk within a [rows]x64-fp16 tile (128B rows)
__device__ __forceinline__ uint32_t swz(uint32_t row, uint32_t chunk) {
    return row * 128u + (((chunk ^ row) & 7u) << 4);
}

// ------------------------- small kernels ------------------------------------
__global__ void k_init() {
    int i = threadIdx.x;
    if (i < NEXP) { g_counts[i] = 0; g_cursor[i] = 0; }
}

// router: one warp handles 4 tokens. Wr is read once per 4 tokens (4x less L1
// traffic than 1 token/warp) while the grid stays large enough (256 CTAs,
// ~60 regs) to keep all SMs occupied and the x stream latency-hidden.
__global__ void k_router(const float* __restrict__ x,
                         const float* __restrict__ Wr,
                         const float* __restrict__ br) {
    int gw   = (blockIdx.x * blockDim.x + threadIdx.x) >> 5;
    int lane = threadIdx.x & 31;
    int t0   = gw * 4;
    if (t0 >= TOK) return;

    float acc[4][8];
#pragma unroll
    for (int t = 0; t < 4; t++)
#pragma unroll
        for (int e = 0; e < NEXP; e++) acc[t][e] = 0.f;

    for (int it = 0; it < DIM / 32; it++) {
        int d = it * 32 + lane;
        float4 w0 = *(const float4*)(Wr + (size_t)d * NEXP);
        float4 w1 = *(const float4*)(Wr + (size_t)d * NEXP + 4);
#pragma unroll
        for (int t = 0; t < 4; t++) {
            float xv = x[(size_t)(t0 + t) * DIM + d];
            acc[t][0] += xv * w0.x; acc[t][1] += xv * w0.y;
            acc[t][2] += xv * w0.z; acc[t][3] += xv * w0.w;
            acc[t][4] += xv * w1.x; acc[t][5] += xv * w1.y;
            acc[t][6] += xv * w1.z; acc[t][7] += xv * w1.w;
        }
    }
#pragma unroll
    for (int t = 0; t < 4; t++)
#pragma unroll
        for (int e = 0; e < NEXP; e++)
#pragma unroll
            for (int off = 16; off > 0; off >>= 1)
                acc[t][e] += __shfl_xor_sync(0xFFFFFFFFu, acc[t][e], off);

    if (lane < 4) {
        int t = lane;
        float best = acc[t][0] + br[0]; int bi = 0;
#pragma unroll
        for (int e = 1; e < NEXP; e++) {
            float v = acc[t][e] + br[e];
            if (v > best) { best = v; bi = e; }
        }
        g_expert[t0 + t] = bi;
        atomicAdd(&g_counts[bi], 1);
    }
}

__global__ void k_scan() {
    if (threadIdx.x == 0) {
        int s = 0;
        for (int e = 0; e < NEXP; e++) {
            g_offsets[e] = s;
            s += (g_counts[e] + 127) & ~127;    // 128-aligned segments
        }
    }
}

__global__ void k_scatter() {
    int t = blockIdx.x * blockDim.x + threadIdx.x;
    if (t >= TOK) return;
    int e = g_expert[t];
    int pos = g_offsets[e] + atomicAdd(&g_cursor[e], 1);
    g_tok[pos] = t;
    g_pos[t]   = pos;
}

// gather + convert x rows into chunked swizzled fp16 layout
__global__ void k_gather16(const float* __restrict__ x) {
    int t   = blockIdx.x;          // token id
    int pos = g_pos[t];
    int b   = threadIdx.x >> 3;    // k-block 0..15
    int c   = threadIdx.x & 7;     // dest 16B chunk position 0..7
    int cc  = c ^ (pos & 7);       // source chunk
    const float4* src = (const float4*)(x + (size_t)t * DIM + b * 64 + cc * 8);
    float4 v0 = src[0], v1 = src[1];
    __half2 h0 = __floats2half2_rn(v0.x, v0.y);
    __half2 h1 = __floats2half2_rn(v0.z, v0.w);
    __half2 h2 = __floats2half2_rn(v1.x, v1.y);
    __half2 h3 = __floats2half2_rn(v1.z, v1.w);
    uint4 o;
    o.x = *(uint32_t*)&h0; o.y = *(uint32_t*)&h1;
    o.z = *(uint32_t*)&h2; o.w = *(uint32_t*)&h3;
    *(uint4*)(g_xa + ((size_t)b * AROWS + pos) * 64 + c * 8) = o;
}

// weights: [e][R=k][C=n] fp32 -> chunked [e][R/64][C][64] fp16, swizzled
__global__ void k_tconv(const float* __restrict__ src,
                        __half* __restrict__ dst, int R, int C) {
    __shared__ float tile[64][33];
    const int e  = blockIdx.z;
    const int kb = blockIdx.y;         // k-block
    const int n0 = blockIdx.x * 32;
    const int KB = R / 64;
    const float* s = src + (size_t)e * R * C + (size_t)kb * 64 * C + n0;
    int tx = threadIdx.x & 31, ty = threadIdx.x >> 5;
#pragma unroll
    for (int i = 0; i < 8; i++)
        tile[ty * 8 + i][tx] = s[(size_t)(ty * 8 + i) * C + tx];
    __syncthreads();
    int c  = threadIdx.x & 7;          // dest chunk position
    int nn = threadIdx.x >> 3;         // 0..31
    int n  = n0 + nn;
    int cc = c ^ (n & 7);              // source chunk
    __half2 h0 = __floats2half2_rn(tile[cc * 8 + 0][nn], tile[cc * 8 + 1][nn]);
    __half2 h1 = __floats2half2_rn(tile[cc * 8 + 2][nn], tile[cc * 8 + 3][nn]);
    __half2 h2 = __floats2half2_rn(tile[cc * 8 + 4][nn], tile[cc * 8 + 5][nn]);
    __half2 h3 = __floats2half2_rn(tile[cc * 8 + 6][nn], tile[cc * 8 + 7][nn]);
    uint4 o;
    o.x = *(uint32_t*)&h0; o.y = *(uint32_t*)&h1;
    o.z = *(uint32_t*)&h2; o.w = *(uint32_t*)&h3;
    *(uint4*)(dst + (((size_t)e * KB + kb) * C + n) * 64 + c * 8) = o;
}

// ------------------------- fp16 HMMA grouped GEMM, bulk producer -------------
// D = A*B. 128x128 CTA tile, 4 warps (128 threads) of 64x64 warp tiles,
// BK=64, 3-stage pipeline (32KB/stage), 2 CTAs/SM.
// Iter c computes stage c%3 and (after the barrier) refills stage (c+2)%3.
template<int KB, int NTOT, bool WRITE_H, bool SCATTER_OUT>
__global__ __launch_bounds__(128, 2)
void k_mma(const __half* __restrict__ A, const __half* __restrict__ B,
           const float* __restrict__ bias, float* __restrict__ OutF,
           __half* __restrict__ Hout) {
    extern __shared__ char smem[];
    __shared__ uint64_t mbar[3];
    const int e   = blockIdx.z;
    const int cnt = g_counts[e];
    const int row0 = blockIdx.y * 128;
    if (row0 >= cnt) return;
    const int base = g_offsets[e];           // 128-aligned
    const int col0 = blockIdx.x * 128;

    const uint32_t sb = smem_u32(smem);
    const int tid  = threadIdx.x;
    const int lane = tid & 31, warp = tid >> 5;
    const int wm = warp & 1, wn = warp >> 1;        // 2 x 2 warp grid, 64x64 tiles

    if (tid == 0) {
#pragma unroll
        for (int s = 0; s < 3; s++) MBAR_INIT(smem_u32(&mbar[s]), 1);
    }
    __syncthreads();

    const __half* Abase = A + ((size_t)base + row0) * 64;
    const __half* Bbase = B + ((size_t)e * KB * NTOT + col0) * 64;
    auto issue = [&](int c) {
        const int s = c % 3;
        const uint32_t st = sb + (uint32_t)s * 32768u;
        const uint32_t mb = smem_u32(&mbar[s]);
        MBAR_EXPECT_TX(mb, 32768u);
        CP_BULK(st,          Abase + (size_t)c * AROWS * 64, 16384u, mb);
        CP_BULK(st + 16384u, Bbase + (size_t)c * NTOT * 64,  16384u, mb);
    };
    if (tid == 0) { issue(0); issue(1); }

    // ---- consumer (ldmatrix) mapping ----
    const uint32_t g  = (uint32_t)lane >> 3;
    const uint32_t lr = (uint32_t)lane & 7;
    const uint32_t rowA = (uint32_t)(wm * 64) + (g & 1) * 8 + lr;
    const uint32_t chA  = g >> 1;
    const uint32_t rowB = (uint32_t)(wn * 64) + (g >> 1) * 8 + lr;
    const uint32_t chB  = g & 1;

    float acc[4][8][4];
#pragma unroll
    for (int i = 0; i < 4; i++)
#pragma unroll
        for (int j = 0; j < 8; j++)
#pragma unroll
            for (int q = 0; q < 4; q++) acc[i][j][q] = 0.f;

    int st_s = 0, ph = 0;
    for (int c = 0; c < KB; c++) {
        MBAR_WAIT(smem_u32(&mbar[st_s]), (uint32_t)ph);

        const uint32_t stc = sb + (uint32_t)st_s * 32768u;
#pragma unroll
        for (int kk = 0; kk < 4; kk++) {
            uint32_t ah[4][4], bb[8][2];
#pragma unroll
            for (int i = 0; i < 4; i++)
                LDSM4(ah[i], stc + swz(rowA + i * 16, kk * 2 + chA));
#pragma unroll
            for (int p = 0; p < 4; p++) {
                uint32_t t4[4];
                LDSM4(t4, stc + 16384u + swz(rowB + p * 16, kk * 2 + chB));
                bb[p * 2][0] = t4[0]; bb[p * 2][1] = t4[1];
                bb[p * 2 + 1][0] = t4[2]; bb[p * 2 + 1][1] = t4[3];
            }
#pragma unroll
            for (int i = 0; i < 4; i++)
#pragma unroll
                for (int j = 0; j < 8; j++) MMA_F16(acc[i][j], ah[i], bb[j]);
        }

        __syncthreads();                       // all warps done with this stage
        if (tid == 0 && c + 2 < KB) issue(c + 2);
        if (++st_s == 3) { st_s = 0; ph ^= 1; }
    }

    // ---- epilogue ----
    const int qr = lane >> 2;
    const int qc = (lane & 3) * 2;
#pragma unroll
    for (int i = 0; i < 4; i++) {
#pragma unroll
        for (int h = 0; h < 2; h++) {
            const int grow = row0 + wm * 64 + i * 16 + qr + h * 8;
            if (grow >= cnt) continue;
#pragma unroll
            for (int j = 0; j < 8; j++) {
                const int col = col0 + wn * 64 + j * 8 + qc;
                float v0 = acc[i][j][h * 2 + 0] + bias[(size_t)e * NTOT + col];
                float v1 = acc[i][j][h * 2 + 1] + bias[(size_t)e * NTOT + col + 1];
                if (WRITE_H) {
                    v0 = 0.5f * v0 * (1.0f + erff(v0 * 0.70710678118654752f));
                    v1 = 0.5f * v1 * (1.0f + erff(v1 * 0.70710678118654752f));
                    size_t row = (size_t)(base + grow);
                    int hb = col >> 6;
                    int cc = (col >> 3) & 7;
                    size_t o = ((size_t)hb * AROWS + row) * 64 +
                               (((uint32_t)cc ^ (uint32_t)(row & 7)) << 3) + qc;
                    __half2 hv = __floats2half2_rn(v0, v1);
                    *(__half2*)(Hout + o) = hv;
                } else {
                    size_t orow = SCATTER_OUT ? (size_t)g_tok[base + grow]
                                              : (size_t)(base + grow);
                    *(float2*)(OutF + orow * NTOT + col) = make_float2(v0, v1);
                }
            }
        }
    }
}

// ------------------------- launch --------------------------------------------
extern "C" void kernel_launch(void* const* d_in, const int* in_sizes, int n_in,
                              void* d_out, int out_size) {
    const float* x  = (const float*)d_in[0];
    const float* Wr = (const float*)d_in[1];
    const float* br = (const float*)d_in[2];
    const float* W1 = (const float*)d_in[3];
    const float* b1 = (const float*)d_in[4];
    const float* W2 = (const float*)d_in[5];
    const float* b2 = (const float*)d_in[6];
    float* out = (float*)d_out;

    __half *xa, *ha, *w1t, *w2t;
    cudaGetSymbolAddress((void**)&xa,  g_xa);
    cudaGetSymbolAddress((void**)&ha,  g_ha);
    cudaGetSymbolAddress((void**)&w1t, g_w1t);
    cudaGetSymbolAddress((void**)&w2t, g_w2t);

    // lazily-created side stream + fork/join events (host objects only; no
    // device memory). The captured WORK is identical on every call.
    static cudaStream_t s2 = nullptr;
    static cudaEvent_t ev0 = nullptr, ev1 = nullptr, ev2 = nullptr;
    if (!s2) {
        cudaStreamCreateWithFlags(&s2, cudaStreamNonBlocking);
        cudaEventCreateWithFlags(&ev0, cudaEventDisableTiming);
        cudaEventCreateWithFlags(&ev1, cudaEventDisableTiming);
        cudaEventCreateWithFlags(&ev2, cudaEventDisableTiming);
    }

    const int SMEM_DYN = 3 * 32768;   // 96KB
    cudaFuncSetAttribute((const void*)k_mma<DIM / 64, HID, true,  false>,
                         cudaFuncAttributeMaxDynamicSharedMemorySize, SMEM_DYN);
    cudaFuncSetAttribute((const void*)k_mma<HID / 64, DIM, false, true>,
                         cudaFuncAttributeMaxDynamicSharedMemorySize, SMEM_DYN);

    // fork: weight-conversion stream (independent of the router chain)
    cudaEventRecord(ev0, 0);
    cudaStreamWaitEvent(s2, ev0, 0);
    k_tconv<<<dim3(HID / 32, DIM / 64, NEXP), 256, 0, s2>>>(W1, w1t, DIM, HID);
    cudaEventRecord(ev1, s2);
    k_tconv<<<dim3(DIM / 32, HID / 64, NEXP), 256, 0, s2>>>(W2, w2t, HID, DIM);
    cudaEventRecord(ev2, s2);

    // main chain: router -> permutation -> gather
    k_init<<<1, 32>>>();
    k_router<<<TOK / 32, 256>>>(x, Wr, br);    // 8 warps/block, 4 tokens/warp
    k_scan<<<1, 32>>>();
    k_scatter<<<TOK / 256, 256>>>();
    k_gather16<<<TOK, 128>>>(x);

    // GEMM1 needs w1t; GEMM2 needs w2t (tconv2 overlaps GEMM1)
    cudaStreamWaitEvent(0, ev1, 0);
    k_mma<DIM / 64, HID, true,  false>
        <<<dim3(HID / 128, TOK / 128, NEXP), 128, SMEM_DYN>>>(xa, w1t, b1, nullptr, ha);
    cudaStreamWaitEvent(0, ev2, 0);
    k_mma<HID / 64, DIM, false, true>
        <<<dim3(DIM / 128, TOK / 128, NEXP), 128, SMEM_DYN>>>(ha, w2t, b2, out, nullptr);
}